// round 14
// baseline (speedup 1.0000x reference)
#include <cuda_runtime.h>

#define FULL 0xFFFFFFFFu

// Problem shape (fixed): N=1, L=S=512, H=8, D=M=32
constexpr int H = 8;
constexpr int NCH = 16;              // 32-row chunks per head
constexpr int NBLOCKS = NCH * H;     // 128 CTAs, wave-1 co-resident
constexpr int MATS = 3 * 1024 + 32;  // KK(1024) SQQ(1024) KV(1024) Ksum(32)
constexpr float K_SCALE = 0.05892556509887896f; // 1/(3*sqrt(32))

// Contiguous partial layout: g_part[cta][elem]  (cta = c*8 + h)
__device__ __align__(16) float g_part[NBLOCKS * MATS];
__device__ __align__(16) float g_mats[H * MATS];
__device__ unsigned g_c1[H * 64];    // per-head monotonic counters, 256B apart
__device__ unsigned g_c2[H * 64];

__device__ __forceinline__ unsigned ld_acq(const unsigned* p) {
    unsigned v;
    asm volatile("ld.acquire.gpu.u32 %0, [%1];" : "=r"(v) : "l"(p) : "memory");
    return v;
}
__device__ __forceinline__ unsigned atom_add_acqrel(unsigned* p, unsigned v) {
    unsigned old;
    asm volatile("atom.acq_rel.gpu.add.u32 %0, [%1], %2;"
                 : "=r"(old) : "l"(p), "r"(v) : "memory");
    return old;
}

// Per-head barrier (validated R6): 16 CTAs rendezvous on a monotonic counter.
__device__ __forceinline__ void head_barrier(unsigned* ctr) {
    __syncthreads();
    if (threadIdx.x == 0) {
        unsigned old = atom_add_acqrel(ctr, 1u);
        unsigned target = (old / NCH) * NCH + NCH;
        while ((int)(ld_acq(ctr) - target) < 0) { }
    }
    __syncthreads();
}

// Shared-memory plan (floats, stride 36 rows = f4-aligned):
//   [0)     sQ (32x36)  -> reused as sT1 in phase C
//   [1152)  sK (32x36)  -> reused as sT2 in phase C
//   [2304)  sV (32x36)
//   [3456)  sQt (32x36) transposed Q
//   [4608)  sKt (32x36) transposed K
//   [5760)  sO1 (32x36)
//   [6912)  sM  (MATS)  KK | SQQ | KV | Ksum
constexpr int OQ = 0, OK = 1152, OV = 2304, OQT = 3456, OKT = 4608,
              OO1 = 5760, OM = 6912, SMEM_F = OM + MATS;   // 10016 floats

__global__ __launch_bounds__(512) void fused_kernel(
        const float* __restrict__ q, const float* __restrict__ k,
        const float* __restrict__ v, const float* __restrict__ klen,
        float* __restrict__ out) {
    __shared__ __align__(16) float sm[SMEM_F];
    float (*sQ)[36]  = (float (*)[36])&sm[OQ];
    float (*sK)[36]  = (float (*)[36])&sm[OK];
    float (*sV)[36]  = (float (*)[36])&sm[OV];
    float (*sQt)[36] = (float (*)[36])&sm[OQT];
    float (*sKt)[36] = (float (*)[36])&sm[OKT];
    float (*sT1)[36] = (float (*)[36])&sm[OQ];    // alias: sQ dead by then
    float (*sT2)[36] = (float (*)[36])&sm[OK];    // alias: sK dead by then
    float (*sO1)[36] = (float (*)[36])&sm[OO1];
    float* sM        = &sm[OM];

    int bx = blockIdx.x;
    int h = bx & 7, c = bx >> 3;
    int tid = threadIdx.x, lane = tid & 31, w = tid >> 5;

    // ================= Phase A: load + LN + partial matrices ===============
    #pragma unroll
    for (int i = tid; i < 768; i += 512) {
        int ten = i >> 8, idx = i & 255;
        int r4 = idx >> 3, c4 = (idx & 7) * 4;
        int g = ((c * 32 + r4) * H + h) * 32 + c4;
        const float* src = (ten == 0) ? q : (ten == 1) ? k : v;
        float (*dst)[36] = (ten == 0) ? sQ : (ten == 1) ? sK : sV;
        *(float4*)&dst[r4][c4] = *(const float4*)&src[g];
    }
    __syncthreads();

    // LN: warp w -> rows w, w+16
    #pragma unroll
    for (int rr = 0; rr < 2; rr++) {
        int r = w + rr * 16;
        float x = sQ[r][lane], y = sK[r][lane];
        float sx = x, sxx = x * x, sy = y, syy = y * y;
        #pragma unroll
        for (int o = 16; o; o >>= 1) {
            sx  += __shfl_xor_sync(FULL, sx,  o);
            sxx += __shfl_xor_sync(FULL, sxx, o);
            sy  += __shfl_xor_sync(FULL, sy,  o);
            syy += __shfl_xor_sync(FULL, syy, o);
        }
        float muq = sx * (1.0f / 32.0f);
        float vq  = fmaf(-muq, muq, sxx * (1.0f / 32.0f));
        sQ[r][lane] = (x - muq) * rsqrtf(vq + 1e-5f);
        float muk = sy * (1.0f / 32.0f);
        float vk  = fmaf(-muk, muk, syy * (1.0f / 32.0f));
        sK[r][lane] = (y - muk) * rsqrtf(vk + 1e-5f) * (K_SCALE * klen[c * 32 + r]);
    }
    __syncthreads();

    // Partial GEMMs: KK(grp0) SQQ(grp1) KV(grp2), 4x2 tiles; Ksum(grp3).
    {
        int grp = tid >> 7, t = tid & 127;
        float* outp = &g_part[(size_t)bx * MATS];
        if (grp < 3) {
            const float (*X)[36] = (grp == 1) ? sQ : sK;
            const float (*Y)[36] = (grp == 0) ? sK : (grp == 1) ? sQ : sV;
            int a0 = (t & 7) * 4, b0 = (t >> 3) * 2;
            float acc[4][2] = {};
            #pragma unroll 4
            for (int r = 0; r < 32; r++) {
                float4 xa = *(const float4*)&X[r][a0];
                float2 yb = *(const float2*)&Y[r][b0];
                float xs[4] = {xa.x, xa.y, xa.z, xa.w};
                #pragma unroll
                for (int i = 0; i < 4; i++) {
                    acc[i][0] = fmaf(xs[i], yb.x, acc[i][0]);
                    acc[i][1] = fmaf(xs[i], yb.y, acc[i][1]);
                }
            }
            int base = grp * 1024;
            #pragma unroll
            for (int i = 0; i < 4; i++)
                *(float2*)&outp[base + (a0 + i) * 32 + b0] =
                    make_float2(acc[i][0], acc[i][1]);
        } else if (t < 32) {
            float s = 0.0f;
            #pragma unroll
            for (int r = 0; r < 32; r++) s += sK[r][t];
            outp[3072 + t] = s;
        }
    }

    head_barrier(&g_c1[h * 64]);

    // ================= Phase B: coalesced slice reduce =====================
    // 1552 float2 per head / 16 CTAs = 97 float2 per CTA.
    if (tid < 97) {
        int e2 = c * 97 + tid;
        float2 s = make_float2(0.f, 0.f);
        #pragma unroll
        for (int cc = 0; cc < NCH; cc++) {
            const float2* pp =
                (const float2*)&g_part[((size_t)(cc * 8 + h)) * MATS];
            float2 a = pp[e2];
            s.x += a.x; s.y += a.y;
        }
        ((float2*)&g_mats[(size_t)h * MATS])[e2] = s;
    }

    head_barrier(&g_c2[h * 64]);

    // ================= Phase C: GEMM epilogue ==============================
    // Stage matrices + transpose Q/K (sQ/sK still live until sT1/sT2 write).
    {
        const float4* m4 = (const float4*)&g_mats[(size_t)h * MATS];
        float4* s4 = (float4*)sM;
        #pragma unroll
        for (int i = tid; i < MATS / 4; i += 512) s4[i] = m4[i];
    }
    {
        int ten = tid >> 8, idx = tid & 255;       // 512 thr: 1 f4 each
        int r4 = idx >> 3, c4 = (idx & 7) * 4;
        float (*S)[36] = (ten == 0) ? sQ : sK;
        float (*T)[36] = (ten == 0) ? sQt : sKt;
        float4 x = *(const float4*)&S[r4][c4];
        T[c4 + 0][r4] = x.x; T[c4 + 1][r4] = x.y;
        T[c4 + 2][r4] = x.z; T[c4 + 3][r4] = x.w;
    }
    __syncthreads();

    // T1 = Q*KK (grp0, overwrites sQ), T2 = K*SQQ (grp1, overwrites sK),
    // O1 = Q*KV (grp2). C[a][b] = sum_d X[d][a] * Y[d][b], 4x2 tiles.
    {
        int grp = tid >> 7, t = tid & 127;
        if (grp < 3) {
            const float (*X)[36] = (grp == 1) ? sKt : sQt;
            const float* Y = &sM[grp * 1024];
            float (*C)[36] = (grp == 0) ? sT1 : (grp == 1) ? sT2 : sO1;
            int a0 = (t & 7) * 4, b0 = (t >> 3) * 2;
            float acc[4][2] = {};
            #pragma unroll 4
            for (int d = 0; d < 32; d++) {
                float4 xa = *(const float4*)&X[d][a0];
                float2 yb = *(const float2*)&Y[d * 32 + b0];
                float xs[4] = {xa.x, xa.y, xa.z, xa.w};
                #pragma unroll
                for (int i = 0; i < 4; i++) {
                    acc[i][0] = fmaf(xs[i], yb.x, acc[i][0]);
                    acc[i][1] = fmaf(xs[i], yb.y, acc[i][1]);
                }
            }
            #pragma unroll
            for (int i = 0; i < 4; i++)
                *(float2*)&C[a0 + i][b0] = make_float2(acc[i][0], acc[i][1]);
        }
    }
    __syncthreads();

    // Rowdot finish: warp w -> rows 2w, 2w+1.
    #pragma unroll
    for (int rr = 0; rr < 2; rr++) {
        int r = w * 2 + rr;
        float ql = sQt[lane][r];
        float kl = sKt[lane][r];
        float tn = ql * fmaf(0.5f, sT1[r][lane], sM[3072 + lane]);
        float tc = 0.5f * kl * sT2[r][lane];
        #pragma unroll
        for (int o = 16; o; o >>= 1) {
            tn += __shfl_xor_sync(FULL, tn, o);
            tc += __shfl_xor_sync(FULL, tc, o);
        }
        int l = c * 32 + r;
        out[(l * H + h) * 32 + lane] =
            (sO1[r][lane] + tc * sV[r][lane]) / tn;
    }
}

extern "C" void kernel_launch(void* const* d_in, const int* in_sizes, int n_in,
                              void* d_out, int out_size) {
    const float* q    = (const float*)d_in[0];
    const float* k    = (const float*)d_in[1];
    const float* v    = (const float*)d_in[2];
    // d_in[3] attn_mask, d_in[4] query_lengths: unused by the reference
    const float* klen = (const float*)d_in[5];
    float* out = (float*)d_out;

    fused_kernel<<<NBLOCKS, 512>>>(q, k, v, klen, out);
}

// round 16
// speedup vs baseline: 1.1530x; 1.1530x over previous
#include <cuda_runtime.h>

#define FULL 0xFFFFFFFFu

// Problem shape (fixed): N=1, L=S=512, H=8, D=M=32
constexpr int H = 8;
constexpr int K1ROWS = 16;           // rows per k1 chunk
constexpr int NCH = 32;              // k1 chunks per head (512/16)
constexpr int MATS = 3 * 1024 + 32;  // KK(1024) SQQ(1024) KV(1024) Ksum(32)
constexpr float K_SCALE = 0.05892556509887896f; // 1/(3*sqrt(32))

// Contiguous partial layout: g_part[cta][elem]  (cta = c*8 + h)
__device__ __align__(16) float g_part[NCH * H * MATS];
__device__ __align__(16) float g_mats[H * MATS];
__device__ __align__(16) float g_Qn[512 * H * 32];
__device__ __align__(16) float g_Kn[512 * H * 32];

// ---------------------------------------------------------------------------
// K1: 256 CTAs (32 chunks x 8 heads) x 256 thr, 16 rows each.
// Short serial chain: K=16 GEMM loops. LN + partial matrices.
// ---------------------------------------------------------------------------
__global__ __launch_bounds__(256) void k1_build(
        const float* __restrict__ q, const float* __restrict__ k,
        const float* __restrict__ v, const float* __restrict__ klen) {
    __shared__ __align__(16) float sQ[K1ROWS][36];
    __shared__ __align__(16) float sK[K1ROWS][36];
    __shared__ __align__(16) float sV[K1ROWS][36];

    int bx = blockIdx.x;
    int h = bx & 7, c = bx >> 3;          // head, 16-row chunk
    int tid = threadIdx.x, lane = tid & 31, w = tid >> 5;

    // ---- load raw tiles: 384 float4 over 256 threads ----
    #pragma unroll
    for (int i = tid; i < 384; i += 256) {
        int ten = i >> 7, idx = i & 127;
        int r4 = idx >> 3, c4 = (idx & 7) * 4;
        int g = ((c * K1ROWS + r4) * H + h) * 32 + c4;
        const float* src = (ten == 0) ? q : (ten == 1) ? k : v;
        float (*dst)[36] = (ten == 0) ? sQ : (ten == 1) ? sK : sV;
        *(float4*)&dst[r4][c4] = *(const float4*)&src[g];
    }
    __syncthreads();

    // ---- LayerNorm: warp w -> rows w, w+8 ----
    #pragma unroll
    for (int rr = 0; rr < 2; rr++) {
        int r = w + rr * 8;
        float x = sQ[r][lane], y = sK[r][lane];
        float sx = x, sxx = x * x, sy = y, syy = y * y;
        #pragma unroll
        for (int o = 16; o; o >>= 1) {
            sx  += __shfl_xor_sync(FULL, sx,  o);
            sxx += __shfl_xor_sync(FULL, sxx, o);
            sy  += __shfl_xor_sync(FULL, sy,  o);
            syy += __shfl_xor_sync(FULL, syy, o);
        }
        float muq = sx * (1.0f / 32.0f);
        float vq  = fmaf(-muq, muq, sxx * (1.0f / 32.0f));
        sQ[r][lane] = (x - muq) * rsqrtf(vq + 1e-5f);
        float muk = sy * (1.0f / 32.0f);
        float vk  = fmaf(-muk, muk, syy * (1.0f / 32.0f));
        sK[r][lane] = (y - muk) * rsqrtf(vk + 1e-5f) * (K_SCALE * klen[c * K1ROWS + r]);
    }
    __syncthreads();

    // ---- persist normalized Q/K: one STG.128 per thread (overlaps GEMM) ----
    {
        int ten = tid >> 7, idx = tid & 127;
        int r4 = idx >> 3, c4 = (idx & 7) * 4;
        int g = ((c * K1ROWS + r4) * H + h) * 32 + c4;
        if (ten == 0) *(float4*)&g_Qn[g] = *(const float4*)&sQ[r4][c4];
        else          *(float4*)&g_Kn[g] = *(const float4*)&sK[r4][c4];
    }

    // ---- partial matrices: KK(0-63) SQQ(64-127) 4x4; KV(128-255) 4x2 ----
    float* outp = &g_part[(size_t)bx * MATS];
    if (tid < 128) {
        int t = tid & 63;
        const float (*X)[36] = (tid < 64) ? sK : sQ;
        int a0 = (t & 7) * 4, b0 = (t >> 3) * 4;
        float acc[4][4] = {};
        #pragma unroll 4
        for (int r = 0; r < K1ROWS; r++) {
            float4 xa = *(const float4*)&X[r][a0];
            float4 yb = *(const float4*)&X[r][b0];
            float xs[4] = {xa.x, xa.y, xa.z, xa.w};
            float ys[4] = {yb.x, yb.y, yb.z, yb.w};
            #pragma unroll
            for (int i = 0; i < 4; i++)
                #pragma unroll
                for (int j = 0; j < 4; j++)
                    acc[i][j] = fmaf(xs[i], ys[j], acc[i][j]);
        }
        int base = (tid < 64) ? 0 : 1024;
        #pragma unroll
        for (int i = 0; i < 4; i++)
            *(float4*)&outp[base + (a0 + i) * 32 + b0] =
                make_float4(acc[i][0], acc[i][1], acc[i][2], acc[i][3]);
    } else {
        // KV[d][m] = sum_r K[r][d] V[r][m], 4x2 tile per thread (128 thr)
        int t = tid - 128;
        int a0 = (t & 7) * 4, b0 = (t >> 3) * 2;
        float acc[4][2] = {};
        #pragma unroll 4
        for (int r = 0; r < K1ROWS; r++) {
            float4 xa = *(const float4*)&sK[r][a0];
            float2 yb = *(const float2*)&sV[r][b0];
            float xs[4] = {xa.x, xa.y, xa.z, xa.w};
            #pragma unroll
            for (int i = 0; i < 4; i++) {
                acc[i][0] = fmaf(xs[i], yb.x, acc[i][0]);
                acc[i][1] = fmaf(xs[i], yb.y, acc[i][1]);
            }
        }
        #pragma unroll
        for (int i = 0; i < 4; i++)
            *(float2*)&outp[2048 + (a0 + i) * 32 + b0] =
                make_float2(acc[i][0], acc[i][1]);
        if (t < 32) {
            float s = 0.0f;
            #pragma unroll
            for (int r = 0; r < K1ROWS; r++) s += sK[r][t];
            outp[3072 + t] = s;
        }
    }
}

// ---------------------------------------------------------------------------
// K2: 32 CTAs (4 per head). Coalesced 32-way reduce into g_mats.
// ---------------------------------------------------------------------------
__global__ __launch_bounds__(256) void k2_reduce() {
    int h = blockIdx.x & 7, p = blockIdx.x >> 3;   // head, quarter
    int tid = threadIdx.x;
    if (tid >= 194) return;
    int f4 = p * 194 + tid;                        // float4 index in [0,776)
    float4 s = make_float4(0.f, 0.f, 0.f, 0.f);
    #pragma unroll
    for (int cc = 0; cc < NCH; cc++) {
        const float4* pp = (const float4*)&g_part[((size_t)(cc * 8 + h)) * MATS];
        float4 a = pp[f4];
        s.x += a.x; s.y += a.y; s.z += a.z; s.w += a.w;
    }
    ((float4*)&g_mats[(size_t)h * MATS])[f4] = s;
}

// ---------------------------------------------------------------------------
// K3: 128 CTAs x 512 thr (unchanged champion). GEMM epilogue:
// T1 = Q*KK, T2 = K*SQQ, O1 = Q*KV (4x2 reg tiles), then per-row dots.
// ---------------------------------------------------------------------------
__global__ __launch_bounds__(512) void k3_consume(
        const float* __restrict__ v, float* __restrict__ out) {
    __shared__ __align__(16) float sQt[32][36];  // transposed: sQt[d][l]
    __shared__ __align__(16) float sKt[32][36];  // transposed: sKt[d][l]
    __shared__ __align__(16) float sV [32][36];  // row-major
    __shared__ __align__(16) float sM [MATS];    // KK | SQQ | KV | Ksum
    __shared__ __align__(16) float sT1[32][36];  // (Q*KK)[l][e]
    __shared__ __align__(16) float sT2[32][36];  // (K*SQQ)[l][e]
    __shared__ __align__(16) float sO1[32][36];  // (Q*KV)[l][m]

    int bx = blockIdx.x;
    int h = bx & 7, c = bx >> 3;
    int tid = threadIdx.x, lane = tid & 31, w = tid >> 5;

    // ---- stage matrices (776 float4 over 512 threads) ----
    {
        const float4* m4 = (const float4*)&g_mats[(size_t)h * MATS];
        float4* s4 = (float4*)sM;
        #pragma unroll
        for (int i = tid; i < MATS / 4; i += 512) s4[i] = m4[i];
    }
    // ---- load Q/K (transpose via STS) and V ----
    #pragma unroll
    for (int i = tid; i < 768; i += 512) {
        int ten = i >> 8, idx = i & 255;
        int r4 = idx >> 3, c4 = (idx & 7) * 4;
        int g = ((c * 32 + r4) * H + h) * 32 + c4;
        if (ten == 2) {
            *(float4*)&sV[r4][c4] = *(const float4*)&v[g];
        } else {
            float4 x = (ten == 0) ? *(const float4*)&g_Qn[g]
                                  : *(const float4*)&g_Kn[g];
            float (*T)[36] = (ten == 0) ? sQt : sKt;
            T[c4 + 0][r4] = x.x; T[c4 + 1][r4] = x.y;
            T[c4 + 2][r4] = x.z; T[c4 + 3][r4] = x.w;
        }
    }
    __syncthreads();

    // ---- 3 GEMMs: C[a][b] = sum_d X[d][a] * Y[d][b], 4x2 tiles ----
    int grp = tid >> 7, t = tid & 127;
    if (grp < 3) {
        const float (*X)[36] = (grp == 1) ? sKt : sQt;   // T1:Q, T2:K, O1:Q
        const float* Y = &sM[grp * 1024];
        float (*C)[36] = (grp == 0) ? sT1 : (grp == 1) ? sT2 : sO1;
        int a0 = (t & 7) * 4, b0 = (t >> 3) * 2;
        float acc[4][2] = {};
        #pragma unroll 4
        for (int d = 0; d < 32; d++) {
            float4 xa = *(const float4*)&X[d][a0];
            float2 yb = *(const float2*)&Y[d * 32 + b0];
            float xs[4] = {xa.x, xa.y, xa.z, xa.w};
            #pragma unroll
            for (int i = 0; i < 4; i++) {
                acc[i][0] = fmaf(xs[i], yb.x, acc[i][0]);
                acc[i][1] = fmaf(xs[i], yb.y, acc[i][1]);
            }
        }
        #pragma unroll
        for (int i = 0; i < 4; i++)
            *(float2*)&C[a0 + i][b0] = make_float2(acc[i][0], acc[i][1]);
    }
    __syncthreads();

    // ---- per-row finish: warp w -> rows 2w, 2w+1 ----
    #pragma unroll
    for (int rr = 0; rr < 2; rr++) {
        int r = w * 2 + rr;
        float ql = sQt[lane][r];
        float kl = sKt[lane][r];
        float tn = ql * fmaf(0.5f, sT1[r][lane], sM[3072 + lane]);
        float tc = 0.5f * kl * sT2[r][lane];
        #pragma unroll
        for (int o = 16; o; o >>= 1) {
            tn += __shfl_xor_sync(FULL, tn, o);
            tc += __shfl_xor_sync(FULL, tc, o);
        }
        int l = c * 32 + r;
        out[(l * H + h) * 32 + lane] =
            (sO1[r][lane] + tc * sV[r][lane]) / tn;
    }
}

extern "C" void kernel_launch(void* const* d_in, const int* in_sizes, int n_in,
                              void* d_out, int out_size) {
    const float* q    = (const float*)d_in[0];
    const float* k    = (const float*)d_in[1];
    const float* v    = (const float*)d_in[2];
    // d_in[3] attn_mask, d_in[4] query_lengths: unused by the reference
    const float* klen = (const float*)d_in[5];
    float* out = (float*)d_out;

    k1_build<<<NCH * H, 256>>>(q, k, v, klen);   // 256 CTAs, 16-row chunks
    k2_reduce<<<4 * H, 256>>>();                 // 32 CTAs
    k3_consume<<<16 * H, 512>>>(v, out);         // 128 CTAs
}

// round 17
// speedup vs baseline: 1.1863x; 1.0288x over previous
#include <cuda_runtime.h>

#define FULL 0xFFFFFFFFu

// Problem shape (fixed): N=1, L=S=512, H=8, D=M=32
constexpr int H = 8;
constexpr int K1ROWS = 64;           // rows per k1 chunk
constexpr int NCH = 8;               // k1 chunks per head (512/64)
constexpr int MATS = 3 * 1024 + 32;  // KK(1024) SQQ(1024) KV(1024) Ksum(32)
constexpr float K_SCALE = 0.05892556509887896f; // 1/(3*sqrt(32))

// Contiguous partial layout: g_part[cta][elem]  (cta = c*8 + h)
__device__ __align__(16) float g_part[NCH * H * MATS];

// ---------------------------------------------------------------------------
// K1: 64 CTAs (8 chunks x 8 heads) x 512 thr, 64 rows each.
// LN + partial KK/SQQ/KV/Ksum. No Qn/Kn persist (consumer recomputes LN).
// ---------------------------------------------------------------------------
__global__ __launch_bounds__(512) void k1_build(
        const float* __restrict__ q, const float* __restrict__ k,
        const float* __restrict__ v, const float* __restrict__ klen) {
    __shared__ __align__(16) float sQ[K1ROWS][36];
    __shared__ __align__(16) float sK[K1ROWS][36];
    __shared__ __align__(16) float sV[K1ROWS][36];

    int bx = blockIdx.x;
    int h = bx & 7, c = bx >> 3;          // head, 64-row chunk
    int tid = threadIdx.x, lane = tid & 31, w = tid >> 5;

    // ---- load raw tiles: 1536 float4 over 512 threads ----
    #pragma unroll
    for (int i = tid; i < 3 * 512; i += 512) {
        int ten = i >> 9, idx = i & 511;
        int r4 = idx >> 3, c4 = (idx & 7) * 4;
        int g = ((c * K1ROWS + r4) * H + h) * 32 + c4;
        const float* src = (ten == 0) ? q : (ten == 1) ? k : v;
        float (*dst)[36] = (ten == 0) ? sQ : (ten == 1) ? sK : sV;
        *(float4*)&dst[r4][c4] = *(const float4*)&src[g];
    }
    __syncthreads();

    // ---- LayerNorm: warp w -> rows w, w+16, w+32, w+48 ----
    #pragma unroll
    for (int rr = 0; rr < 4; rr++) {
        int r = w + rr * 16;
        float x = sQ[r][lane], y = sK[r][lane];
        float sx = x, sxx = x * x, sy = y, syy = y * y;
        #pragma unroll
        for (int o = 16; o; o >>= 1) {
            sx  += __shfl_xor_sync(FULL, sx,  o);
            sxx += __shfl_xor_sync(FULL, sxx, o);
            sy  += __shfl_xor_sync(FULL, sy,  o);
            syy += __shfl_xor_sync(FULL, syy, o);
        }
        float muq = sx * (1.0f / 32.0f);
        float vq  = fmaf(-muq, muq, sxx * (1.0f / 32.0f));
        sQ[r][lane] = (x - muq) * rsqrtf(vq + 1e-5f);
        float muk = sy * (1.0f / 32.0f);
        float vk  = fmaf(-muk, muk, syy * (1.0f / 32.0f));
        sK[r][lane] = (y - muk) * rsqrtf(vk + 1e-5f) * (K_SCALE * klen[c * K1ROWS + r]);
    }
    __syncthreads();

    // ---- partial GEMMs: KK(grp0) SQQ(grp1) KV(grp2) 4x2, Ksum(grp3) ----
    int grp = tid >> 7, t = tid & 127;
    float* outp = &g_part[(size_t)bx * MATS];
    if (grp < 3) {
        const float (*X)[36] = (grp == 1) ? sQ : sK;
        const float (*Y)[36] = (grp == 0) ? sK : (grp == 1) ? sQ : sV;
        int a0 = (t & 7) * 4, b0 = (t >> 3) * 2;
        float acc[4][2] = {};
        #pragma unroll 4
        for (int r = 0; r < K1ROWS; r++) {
            float4 xa = *(const float4*)&X[r][a0];
            float2 yb = *(const float2*)&Y[r][b0];
            float xs[4] = {xa.x, xa.y, xa.z, xa.w};
            #pragma unroll
            for (int i = 0; i < 4; i++) {
                acc[i][0] = fmaf(xs[i], yb.x, acc[i][0]);
                acc[i][1] = fmaf(xs[i], yb.y, acc[i][1]);
            }
        }
        int base = grp * 1024;
        #pragma unroll
        for (int i = 0; i < 4; i++)
            *(float2*)&outp[base + (a0 + i) * 32 + b0] =
                make_float2(acc[i][0], acc[i][1]);
    } else if (t < 32) {
        float s = 0.0f;
        #pragma unroll
        for (int r = 0; r < K1ROWS; r++) s += sK[r][t];
        outp[3072 + t] = s;
    }
}

// ---------------------------------------------------------------------------
// K2: 128 CTAs x 512 thr, 32 output rows each.
// Reduces its head's 8 partials straight into smem (coalesced f4, MLP 8),
// recomputes LN for its rows, then GEMM epilogue + rowdot.
// ---------------------------------------------------------------------------
__global__ __launch_bounds__(512) void k2_consume(
        const float* __restrict__ q, const float* __restrict__ k,
        const float* __restrict__ v, const float* __restrict__ klen,
        float* __restrict__ out) {
    __shared__ __align__(16) float sQt[32][36];  // transposed: sQt[d][l]
    __shared__ __align__(16) float sKt[32][36];  // transposed: sKt[d][l]
    __shared__ __align__(16) float sV [32][36];  // row-major
    __shared__ __align__(16) float sM [MATS];    // KK | SQQ | KV | Ksum
    __shared__ __align__(16) float sT1[32][36];  // (Q*KK)[l][e]
    __shared__ __align__(16) float sT2[32][36];  // (K*SQQ)[l][e]
    __shared__ __align__(16) float sO1[32][36];  // (Q*KV)[l][m]

    int bx = blockIdx.x;
    int h = bx & 7, c = bx >> 3;          // head, 32-row chunk
    int tid = threadIdx.x, lane = tid & 31, w = tid >> 5;

    // ---- reduce this head's 8 partials into sM (776 f4 slots, 2/thread) ----
    {
        float4* s4 = (float4*)sM;
        for (int i = tid; i < MATS / 4; i += 512) {
            float4 s = make_float4(0.f, 0.f, 0.f, 0.f);
            #pragma unroll
            for (int cc = 0; cc < NCH; cc++) {
                const float4* pp =
                    (const float4*)&g_part[((size_t)(cc * 8 + h)) * MATS];
                float4 a = pp[i];
                s.x += a.x; s.y += a.y; s.z += a.z; s.w += a.w;
            }
            s4[i] = s;
        }
    }

    // ---- recompute LN for this CTA's 32 rows (warp w -> rows 2w, 2w+1),
    //      store transposed ----
    #pragma unroll
    for (int rr = 0; rr < 2; rr++) {
        int r = w * 2 + rr;
        int l = c * 32 + r;
        int g = (l * H + h) * 32 + lane;
        float x = q[g], y = k[g];
        float sx = x, sxx = x * x, sy = y, syy = y * y;
        #pragma unroll
        for (int o = 16; o; o >>= 1) {
            sx  += __shfl_xor_sync(FULL, sx,  o);
            sxx += __shfl_xor_sync(FULL, sxx, o);
            sy  += __shfl_xor_sync(FULL, sy,  o);
            syy += __shfl_xor_sync(FULL, syy, o);
        }
        float muq = sx * (1.0f / 32.0f);
        float vq  = fmaf(-muq, muq, sxx * (1.0f / 32.0f));
        sQt[lane][r] = (x - muq) * rsqrtf(vq + 1e-5f);
        float muk = sy * (1.0f / 32.0f);
        float vk  = fmaf(-muk, muk, syy * (1.0f / 32.0f));
        sKt[lane][r] = (y - muk) * rsqrtf(vk + 1e-5f) * (K_SCALE * klen[l]);
    }

    // ---- V tile (row-major, 256 f4 over first 256 threads) ----
    if (tid < 256) {
        int r4 = tid >> 3, c4 = (tid & 7) * 4;
        int g = ((c * 32 + r4) * H + h) * 32 + c4;
        *(float4*)&sV[r4][c4] = *(const float4*)&v[g];
    }
    __syncthreads();

    // ---- 3 GEMMs: C[a][b] = sum_d X[d][a] * Y[d][b], 4x2 tiles ----
    int grp = tid >> 7, t = tid & 127;
    if (grp < 3) {
        const float (*X)[36] = (grp == 1) ? sKt : sQt;   // T1:Q, T2:K, O1:Q
        const float* Y = &sM[grp * 1024];
        float (*C)[36] = (grp == 0) ? sT1 : (grp == 1) ? sT2 : sO1;
        int a0 = (t & 7) * 4, b0 = (t >> 3) * 2;
        float acc[4][2] = {};
        #pragma unroll 4
        for (int d = 0; d < 32; d++) {
            float4 xa = *(const float4*)&X[d][a0];
            float2 yb = *(const float2*)&Y[d * 32 + b0];
            float xs[4] = {xa.x, xa.y, xa.z, xa.w};
            #pragma unroll
            for (int i = 0; i < 4; i++) {
                acc[i][0] = fmaf(xs[i], yb.x, acc[i][0]);
                acc[i][1] = fmaf(xs[i], yb.y, acc[i][1]);
            }
        }
        #pragma unroll
        for (int i = 0; i < 4; i++)
            *(float2*)&C[a0 + i][b0] = make_float2(acc[i][0], acc[i][1]);
    }
    __syncthreads();

    // ---- per-row finish: warp w -> rows 2w, 2w+1 ----
    #pragma unroll
    for (int rr = 0; rr < 2; rr++) {
        int r = w * 2 + rr;
        float ql = sQt[lane][r];
        float kl = sKt[lane][r];
        float tn = ql * fmaf(0.5f, sT1[r][lane], sM[3072 + lane]);
        float tc = 0.5f * kl * sT2[r][lane];
        #pragma unroll
        for (int o = 16; o; o >>= 1) {
            tn += __shfl_xor_sync(FULL, tn, o);
            tc += __shfl_xor_sync(FULL, tc, o);
        }
        int l = c * 32 + r;
        out[(l * H + h) * 32 + lane] =
            (sO1[r][lane] + tc * sV[r][lane]) / tn;
    }
}

extern "C" void kernel_launch(void* const* d_in, const int* in_sizes, int n_in,
                              void* d_out, int out_size) {
    const float* q    = (const float*)d_in[0];
    const float* k    = (const float*)d_in[1];
    const float* v    = (const float*)d_in[2];
    // d_in[3] attn_mask, d_in[4] query_lengths: unused by the reference
    const float* klen = (const float*)d_in[5];
    float* out = (float*)d_out;

    k1_build<<<NCH * H, 512>>>(q, k, v, klen);       // 64 CTAs
    k2_consume<<<16 * H, 512>>>(q, k, v, klen, out); // 128 CTAs
}